// round 15
// baseline (speedup 1.0000x reference)
#include <cuda_runtime.h>
#include <cuda_fp16.h>
#include <cstdint>
#include <math.h>

#define NROWS 4096
#define DIM   1024
#define TEMP_INV 20.0f
#define EPS 1e-8f

#define BM 128
#define BN 128
#define BK 64
#define NKT (DIM / BK)        // 16 k-tiles
#define ROWB 128              // smem row stride in bytes (XOR swizzle, 8 chunks)
#define MAT_BYTES (128 * ROWB)        // 16384 per matrix per stage
#define OFF_A 0
#define OFF_B MAT_BYTES
#define STAGE  (2 * MAT_BYTES)        // 32768
#define NSTG   3
#define SMEM_TOTAL (NSTG * STAGE)     // 98304 -> 2 CTAs/SM

// swizzled byte offset: row r (0..127), 16B chunk c (0..7)
#define SWZ_OFF(r, c) ((r) * ROWB + ((((c) ^ ((r) & 7))) << 4))

// fp16 normalized inputs (allocation-free scratch)
__device__ __half g_xh[NROWS * DIM];
__device__ __half g_yh[NROWS * DIM];

// ---------------------------------------------------------------------------
// helpers
// ---------------------------------------------------------------------------
__device__ __forceinline__ uint32_t smem_to_u32(const void* p) {
    uint32_t a;
    asm("{ .reg .u64 t; cvta.to.shared.u64 t, %1; cvt.u32.u64 %0, t; }"
        : "=r"(a) : "l"(p));
    return a;
}

__device__ __forceinline__ void cp_async16(uint32_t s, const void* g) {
    asm volatile("cp.async.cg.shared.global [%0], [%1], 16;" :: "r"(s), "l"(g));
}

__device__ __forceinline__ void ldsm_x4(uint32_t& r0, uint32_t& r1,
                                        uint32_t& r2, uint32_t& r3, uint32_t addr) {
    asm volatile("ldmatrix.sync.aligned.m8n8.x4.shared.b16 {%0,%1,%2,%3}, [%4];"
                 : "=r"(r0), "=r"(r1), "=r"(r2), "=r"(r3) : "r"(addr));
}

__device__ __forceinline__ void mma16816(float* d, const uint32_t* a,
                                         uint32_t b0, uint32_t b1) {
    asm volatile(
        "mma.sync.aligned.m16n8k16.row.col.f32.f16.f16.f32 "
        "{%0,%1,%2,%3}, {%4,%5,%6,%7}, {%8,%9}, {%0,%1,%2,%3};"
        : "+f"(d[0]), "+f"(d[1]), "+f"(d[2]), "+f"(d[3])
        : "r"(a[0]), "r"(a[1]), "r"(a[2]), "r"(a[3]), "r"(b0), "r"(b1));
}

// ---------------------------------------------------------------------------
// Kernel 1: normalize rows, emit fp16. One warp per row, no block sync.
// ---------------------------------------------------------------------------
__global__ __launch_bounds__(256) void normalize_kernel(
    const float* __restrict__ x, const float* __restrict__ y) {
    const int lane = threadIdx.x & 31;
    const int row = blockIdx.x * 8 + (threadIdx.x >> 5);

    const float* src;
    __half* dst;
    if (row < NROWS) {
        src = x + (size_t)row * DIM;
        dst = g_xh + (size_t)row * DIM;
    } else {
        src = y + (size_t)(row - NROWS) * DIM;
        dst = g_yh + (size_t)(row - NROWS) * DIM;
    }

    float4 v[8];
    float s = 0.0f;
    #pragma unroll
    for (int i = 0; i < 8; i++) {
        v[i] = ((const float4*)src)[lane + i * 32];
        s += v[i].x * v[i].x + v[i].y * v[i].y + v[i].z * v[i].z + v[i].w * v[i].w;
    }
    #pragma unroll
    for (int o = 16; o; o >>= 1) s += __shfl_xor_sync(0xffffffffu, s, o);
    float inv = 1.0f / fmaxf(sqrtf(s), EPS);

    #pragma unroll
    for (int i = 0; i < 8; i++) {
        __half2 p0 = __floats2half2_rn(v[i].x * inv, v[i].y * inv);
        __half2 p1 = __floats2half2_rn(v[i].z * inv, v[i].w * inv);
        ((uint2*)dst)[lane + i * 32] = make_uint2(*(uint32_t*)&p0, *(uint32_t*)&p1);
    }
}

// ---------------------------------------------------------------------------
// Kernel 2: fp16 HMMA GEMM. C[n][m] = 20 * (xn[n] . yn[m])
// 128x128 CTA tile, BK=64, 3-stage cp.async pipeline, 8 warps (2x4),
// warp tile 64x32, 2 CTAs/SM => 4 warps/SMSP for latency coverage.
// Constant stage bases (peel + group-of-3), precomputed ldsm addresses,
// split-issue cp.async, single barrier per kt.
// ---------------------------------------------------------------------------
__global__ __launch_bounds__(256, 2) void gemm_hmma(float* __restrict__ C) {
    extern __shared__ __align__(128) char smem[];
    const int tid = threadIdx.x;
    const int lane = tid & 31;
    const int wid = tid >> 5;
    const int wm = wid >> 2;       // 0..1  (M)
    const int wn = wid & 3;        // 0..3  (N)
    const int bx = blockIdx.x;     // N tile
    const int by = blockIdx.y;     // M tile

    const uint32_t sbase = smem_to_u32(smem);
    const uint32_t S0 = sbase, S1 = sbase + STAGE, S2 = sbase + 2 * STAGE;

    const __half* __restrict__ A = g_xh + (size_t)(by * BM) * DIM;
    const __half* __restrict__ B = g_yh + (size_t)(bx * BN) * DIM;

    // cp.async per-thread mapping: 1024 chunks per matrix over 256 threads
    // = 4 slots/thread/matrix; identical index pattern for A and B.
    uint32_t cp_so[4], cp_go[4];
    #pragma unroll
    for (int i = 0; i < 4; i++) {
        int idx = tid + i * 256;
        int row = idx >> 3;
        int ch  = idx & 7;
        cp_so[i] = SWZ_OFF(row, ch);
        cp_go[i] = (uint32_t)(row * DIM + ch * 8);
    }

    // fill one half (2 chunks x 2 matrices per thread) of buffer 'fsb'
    auto load_half = [&](uint32_t fsb, const __half* gA, const __half* gB, int half) {
        #pragma unroll
        for (int i = half * 2; i < half * 2 + 2; i++) {
            cp_async16(fsb + OFF_A + cp_so[i], gA + cp_go[i]);
            cp_async16(fsb + OFF_B + cp_so[i], gB + cp_go[i]);
        }
    };
    auto commit = [] { asm volatile("cp.async.commit_group;" ::: "memory"); };

    float acc[4][4][4];
    #pragma unroll
    for (int i = 0; i < 4; i++)
        #pragma unroll
        for (int j = 0; j < 4; j++)
            #pragma unroll
            for (int k = 0; k < 4; k++) acc[i][j][k] = 0.0f;

    load_half(S0, A, B, 0);           load_half(S0, A, B, 1);           commit();
    load_half(S1, A + BK, B + BK, 0); load_half(S1, A + BK, B + BK, 1); commit();

    // -------- ldsm address precomputation --------
    // addr(r, c=ks*2+chi) = r*ROWB + ((chi^(r&1))<<4) + ((ks^pm)<<5)
    const int arow = wm * 64 + (lane & 15);
    const int brow = wn * 32 + (lane & 15);
    const int chi  = lane >> 4;
    const int pm   = (lane >> 1) & 3;

    uint32_t abase[4], bbase[2], koff[4];
    #pragma unroll
    for (int mi = 0; mi < 4; mi++) {
        int r = arow + mi * 16;
        abase[mi] = (uint32_t)(r * ROWB + ((chi ^ (r & 1)) << 4)) + OFF_A;
    }
    #pragma unroll
    for (int nj = 0; nj < 2; nj++) {
        int rb = brow + nj * 16;
        bbase[nj] = (uint32_t)(rb * ROWB + ((chi ^ (rb & 1)) << 4)) + OFF_B;
    }
    #pragma unroll
    for (int ks = 0; ks < 4; ks++) koff[ks] = (uint32_t)((ks ^ pm) << 5);

    uint32_t a[4][4], b[2][4];

    auto ld_frags = [&](uint32_t sb, int ks) {
        const uint32_t t = sb + koff[ks];
        #pragma unroll
        for (int mi = 0; mi < 4; mi++)
            ldsm_x4(a[mi][0], a[mi][1], a[mi][2], a[mi][3], t + abase[mi]);
        #pragma unroll
        for (int nj = 0; nj < 2; nj++)
            ldsm_x4(b[nj][0], b[nj][1], b[nj][2], b[nj][3], t + bbase[nj]);
    };
    auto mma_block = [&] {
        #pragma unroll
        for (int mi = 0; mi < 4; mi++) {
            #pragma unroll
            for (int nt = 0; nt < 4; nt++) {
                const int nj = nt >> 1, h = nt & 1;
                mma16816(acc[mi][nt], a[mi], b[nj][h], b[nj][h + 2]);
            }
        }
    };

    // one k-tile on buffer 'sb'; optionally fill 'fsb' from gA/gB
    auto do_kt = [&](uint32_t sb, uint32_t fsb,
                     const __half* gA, const __half* gB, bool pf, bool last) {
        ld_frags(sb, 0);
        mma_block();
        if (pf) load_half(fsb, gA, gB, 0);

        ld_frags(sb, 1);
        mma_block();
        if (pf) load_half(fsb, gA, gB, 1);
        commit();                       // one group per kt (may be empty)

        ld_frags(sb, 2);
        mma_block();

        ld_frags(sb, 3);
        mma_block();

        if (!last) {
            asm volatile("cp.async.wait_group 1;" ::: "memory");
            __syncthreads();
        }
    };

    // prologue: stage 0 resident
    asm volatile("cp.async.wait_group 1;" ::: "memory");
    __syncthreads();

    // peel kt=0 (buffer S0; fills stage 2 -> S2)
    do_kt(S0, S2, A + 2 * BK, B + 2 * BK, true, false);

    const __half* pA = A + 3 * BK;   // stage kt+2 pointer for kt = 1
    const __half* pB = B + 3 * BK;

    for (int g = 0; g < 5; g++) {
        const int kt = 1 + 3 * g;
        const bool lastg = (g == 4);

        do_kt(S1, S0, pA, pB, kt + 2 < NKT, false);
        do_kt(S2, S1, pA + BK, pB + BK, kt + 3 < NKT, false);
        do_kt(S0, S2, pA + 2 * BK, pB + 2 * BK, kt + 4 < NKT, lastg);

        pA += 3 * BK;
        pB += 3 * BK;
    }

    // epilogue: scale by 20, direct float2 stores
    const int erow = by * BM + wm * 64 + (lane >> 2);
    const int ecol = bx * BN + wn * 32 + (lane & 3) * 2;
    #pragma unroll
    for (int mi = 0; mi < 4; mi++) {
        #pragma unroll
        for (int nt = 0; nt < 4; nt++) {
            float* p0 = C + (size_t)(erow + mi * 16) * NROWS + ecol + nt * 8;
            float* p1 = p0 + 8 * NROWS;
            *(float2*)p0 = make_float2(acc[mi][nt][0] * TEMP_INV,
                                       acc[mi][nt][1] * TEMP_INV);
            *(float2*)p1 = make_float2(acc[mi][nt][2] * TEMP_INV,
                                       acc[mi][nt][3] * TEMP_INV);
        }
    }
}

extern "C" void kernel_launch(void* const* d_in, const int* in_sizes, int n_in,
                              void* d_out, int out_size) {
    const float* x = (const float*)d_in[0];
    const float* y = (const float*)d_in[1];
    float* out = (float*)d_out;

    normalize_kernel<<<2 * NROWS / 8, 256>>>(x, y);

    cudaFuncSetAttribute(gemm_hmma,
                         cudaFuncAttributeMaxDynamicSharedMemorySize, SMEM_TOTAL);
    dim3 grid(NROWS / BN, NROWS / BM);
    gemm_hmma<<<grid, 256, SMEM_TOTAL>>>(out);
}

// round 16
// speedup vs baseline: 1.1714x; 1.1714x over previous
#include <cuda_runtime.h>
#include <cuda_fp16.h>
#include <cstdint>
#include <math.h>

#define NROWS 4096
#define DIM   1024
#define TEMP_INV 20.0f
#define EPS 1e-8f

#define BM 128
#define BN 128
#define BK 64
#define NKT (DIM / BK)        // 16 k-tiles
#define ROWB 128              // smem row stride in bytes (XOR swizzle, 8 chunks)
#define MAT_BYTES (128 * ROWB)        // 16384 per matrix per stage
#define OFF_A 0
#define OFF_B MAT_BYTES
#define STAGE  (2 * MAT_BYTES)        // 32768
#define NSTG   3
#define SMEM_TOTAL (NSTG * STAGE)     // 98304 -> 2 CTAs/SM

// swizzled byte offset: row r (0..127), 16B chunk c (0..7)
#define SWZ_OFF(r, c) ((r) * ROWB + ((((c) ^ ((r) & 7))) << 4))

// fp16 normalized inputs (x pre-scaled by 20 = 1/TEMP); alloc-free scratch
__device__ __half g_xh[NROWS * DIM];
__device__ __half g_yh[NROWS * DIM];

// ---------------------------------------------------------------------------
// helpers
// ---------------------------------------------------------------------------
__device__ __forceinline__ uint32_t smem_to_u32(const void* p) {
    uint32_t a;
    asm("{ .reg .u64 t; cvta.to.shared.u64 t, %1; cvt.u32.u64 %0, t; }"
        : "=r"(a) : "l"(p));
    return a;
}

__device__ __forceinline__ void cp_async16(uint32_t s, const void* g) {
    asm volatile("cp.async.cg.shared.global [%0], [%1], 16;" :: "r"(s), "l"(g));
}

__device__ __forceinline__ void ldsm_x4(uint32_t& r0, uint32_t& r1,
                                        uint32_t& r2, uint32_t& r3, uint32_t addr) {
    asm volatile("ldmatrix.sync.aligned.m8n8.x4.shared.b16 {%0,%1,%2,%3}, [%4];"
                 : "=r"(r0), "=r"(r1), "=r"(r2), "=r"(r3) : "r"(addr));
}

__device__ __forceinline__ void mma16816(float* d, const uint32_t* a,
                                         uint32_t b0, uint32_t b1) {
    asm volatile(
        "mma.sync.aligned.m16n8k16.row.col.f32.f16.f16.f32 "
        "{%0,%1,%2,%3}, {%4,%5,%6,%7}, {%8,%9}, {%0,%1,%2,%3};"
        : "+f"(d[0]), "+f"(d[1]), "+f"(d[2]), "+f"(d[3])
        : "r"(a[0]), "r"(a[1]), "r"(a[2]), "r"(a[3]), "r"(b0), "r"(b1));
}

// ---------------------------------------------------------------------------
// Kernel 1: normalize rows, emit fp16. One warp per row, no block sync.
// x rows are additionally scaled by 20 (1/TEMP) so the GEMM epilogue is
// a pure store (product picks up the factor exactly once).
// ---------------------------------------------------------------------------
__global__ __launch_bounds__(256) void normalize_kernel(
    const float* __restrict__ x, const float* __restrict__ y) {
    const int lane = threadIdx.x & 31;
    const int row = blockIdx.x * 8 + (threadIdx.x >> 5);

    const float* src;
    __half* dst;
    float scale;
    if (row < NROWS) {
        src = x + (size_t)row * DIM;
        dst = g_xh + (size_t)row * DIM;
        scale = TEMP_INV;
    } else {
        src = y + (size_t)(row - NROWS) * DIM;
        dst = g_yh + (size_t)(row - NROWS) * DIM;
        scale = 1.0f;
    }

    float4 v[8];
    float s = 0.0f;
    #pragma unroll
    for (int i = 0; i < 8; i++) {
        v[i] = ((const float4*)src)[lane + i * 32];
        s += v[i].x * v[i].x + v[i].y * v[i].y + v[i].z * v[i].z + v[i].w * v[i].w;
    }
    #pragma unroll
    for (int o = 16; o; o >>= 1) s += __shfl_xor_sync(0xffffffffu, s, o);
    float inv = scale / fmaxf(sqrtf(s), EPS);

    #pragma unroll
    for (int i = 0; i < 8; i++) {
        __half2 p0 = __floats2half2_rn(v[i].x * inv, v[i].y * inv);
        __half2 p1 = __floats2half2_rn(v[i].z * inv, v[i].w * inv);
        ((uint2*)dst)[lane + i * 32] = make_uint2(*(uint32_t*)&p0, *(uint32_t*)&p1);
    }
}

// ---------------------------------------------------------------------------
// Kernel 2: fp16 HMMA GEMM. C[n][m] = (20*xn[n]) . yn[m]
// 128x128 CTA tile, BK=64, 3-stage cp.async pipeline, 4 warps (2x2),
// warp tile 64x64, register double-buffered frags, 2 CTAs/SM.
// This round: scalarized addressing (no offset arrays -> no spills),
// pure-store epilogue.
// ---------------------------------------------------------------------------
__global__ __launch_bounds__(128, 2) void gemm_hmma(float* __restrict__ C) {
    extern __shared__ __align__(128) char smem[];
    const int tid = threadIdx.x;
    const int lane = tid & 31;
    const int wid = tid >> 5;
    const int wm = wid >> 1;       // 0..1  (M)
    const int wn = wid & 1;        // 0..1  (N)
    const int bx = blockIdx.x;     // N tile
    const int by = blockIdx.y;     // M tile

    const uint32_t sbase = smem_to_u32(smem);
    const uint32_t S0 = sbase, S1 = sbase + STAGE, S2 = sbase + 2 * STAGE;

    const __half* __restrict__ A = g_xh + (size_t)(by * BM) * DIM;
    const __half* __restrict__ B = g_yh + (size_t)(bx * BN) * DIM;

    // --- cp.async scalar addressing ---
    // slot i (0..7): row = (tid>>3) + 16*i, ch = tid&7  (row&7 invariant)
    // smem offset  = so0 + 2048*i ; global offset = gbase + 16*i*DIM
    const int cprow = tid >> 3;
    const int cpch  = tid & 7;
    const uint32_t so0 = (uint32_t)SWZ_OFF(cprow, cpch);
    const __half* At = A + (size_t)cprow * DIM + cpch * 8;   // thread base
    const __half* Bt = B + (size_t)cprow * DIM + cpch * 8;

    // fill one half (4 slots x 2 matrices) of buffer 'fsb' from thread-based
    // stage pointers gA/gB (= At/Bt + kt*BK)
    auto load_half = [&](uint32_t fsb, const __half* gA, const __half* gB, int half) {
        #pragma unroll
        for (int i = half * 4; i < half * 4 + 4; i++) {
            cp_async16(fsb + OFF_A + so0 + i * 2048, gA + i * 16 * DIM);
            cp_async16(fsb + OFF_B + so0 + i * 2048, gB + i * 16 * DIM);
        }
    };
    auto commit = [] { asm volatile("cp.async.commit_group;" ::: "memory"); };

    float acc[4][8][4];
    #pragma unroll
    for (int i = 0; i < 4; i++)
        #pragma unroll
        for (int j = 0; j < 8; j++)
            #pragma unroll
            for (int k = 0; k < 4; k++) acc[i][j][k] = 0.0f;

    load_half(S0, At, Bt, 0);           load_half(S0, At, Bt, 1);           commit();
    load_half(S1, At + BK, Bt + BK, 0); load_half(S1, At + BK, Bt + BK, 1); commit();

    // --- ldsm scalar addressing ---
    // addr(r=arow+16mi, c=ks*2+chi) = abase0 + 2048*mi + ((ks<<5)^koff0)
    const int arow = wm * 64 + (lane & 15);
    const int brow = wn * 64 + (lane & 15);
    const int chi  = lane >> 4;
    const uint32_t koff0 = (uint32_t)(((lane >> 1) & 3) << 5);
    const uint32_t abase0 =
        (uint32_t)(arow * ROWB + ((chi ^ (arow & 1)) << 4)) + OFF_A;
    const uint32_t bbase0 =
        (uint32_t)(brow * ROWB + ((chi ^ (brow & 1)) << 4)) + OFF_B;

    uint32_t a[2][4][4], b[2][4][4];

    auto ld_frags = [&](uint32_t sb, int ks, uint32_t af[4][4], uint32_t bf[4][4]) {
        const uint32_t t = sb + ((uint32_t)(ks << 5) ^ koff0);
        const uint32_t ta = t + abase0;
        const uint32_t tb = t + bbase0;
        #pragma unroll
        for (int mi = 0; mi < 4; mi++)
            ldsm_x4(af[mi][0], af[mi][1], af[mi][2], af[mi][3], ta + mi * 2048);
        #pragma unroll
        for (int nj = 0; nj < 4; nj++)
            ldsm_x4(bf[nj][0], bf[nj][1], bf[nj][2], bf[nj][3], tb + nj * 2048);
    };
    auto mma_block = [&](uint32_t af[4][4], uint32_t bf[4][4]) {
        #pragma unroll
        for (int mi = 0; mi < 4; mi++) {
            #pragma unroll
            for (int nt = 0; nt < 8; nt++) {
                const int nj = nt >> 1, h = nt & 1;
                mma16816(acc[mi][nt], af[mi], bf[nj][h], bf[nj][h + 2]);
            }
        }
    };

    // one k-tile on buffer 'sb'; optionally fill 'fsb' from gA/gB
    auto do_kt = [&](uint32_t sb, uint32_t fsb,
                     const __half* gA, const __half* gB, bool pf, bool last) {
        ld_frags(sb, 1, a[1], b[1]);
        mma_block(a[0], b[0]);
        if (pf) load_half(fsb, gA, gB, 0);

        ld_frags(sb, 2, a[0], b[0]);
        mma_block(a[1], b[1]);
        if (pf) load_half(fsb, gA, gB, 1);
        commit();                       // one group per kt (may be empty)

        ld_frags(sb, 3, a[1], b[1]);
        mma_block(a[0], b[0]);
        mma_block(a[1], b[1]);

        if (!last) {
            asm volatile("cp.async.wait_group 1;" ::: "memory");
            __syncthreads();
        }
    };

    // prologue: stage 0 resident, prefetch its ks0
    asm volatile("cp.async.wait_group 1;" ::: "memory");
    __syncthreads();
    ld_frags(S0, 0, a[0], b[0]);

    // peel kt=0 (buffer S0; fills stage 2 -> S2)
    do_kt(S0, S2, At + 2 * BK, Bt + 2 * BK, true, false);
    ld_frags(S1, 0, a[0], b[0]);

    const __half* pA = At + 3 * BK;  // stage kt+2 pointer for kt = 1
    const __half* pB = Bt + 3 * BK;

    for (int g = 0; g < 5; g++) {
        const int kt = 1 + 3 * g;
        const bool lastg = (g == 4);

        do_kt(S1, S0, pA, pB, kt + 2 < NKT, false);
        ld_frags(S2, 0, a[0], b[0]);

        do_kt(S2, S1, pA + BK, pB + BK, kt + 3 < NKT, false);
        ld_frags(S0, 0, a[0], b[0]);

        do_kt(S0, S2, pA + 2 * BK, pB + 2 * BK, kt + 4 < NKT, lastg);
        if (!lastg) ld_frags(S1, 0, a[0], b[0]);

        pA += 3 * BK;
        pB += 3 * BK;
    }

    // epilogue: pure float2 stores (scale folded into x-normalize)
    const int erow = by * BM + wm * 64 + (lane >> 2);
    const int ecol = bx * BN + wn * 64 + (lane & 3) * 2;
    #pragma unroll
    for (int mi = 0; mi < 4; mi++) {
        #pragma unroll
        for (int nt = 0; nt < 8; nt++) {
            float* p0 = C + (size_t)(erow + mi * 16) * NROWS + ecol + nt * 8;
            float* p1 = p0 + 8 * NROWS;
            *(float2*)p0 = make_float2(acc[mi][nt][0], acc[mi][nt][1]);
            *(float2*)p1 = make_float2(acc[mi][nt][2], acc[mi][nt][3]);
        }
    }
}

extern "C" void kernel_launch(void* const* d_in, const int* in_sizes, int n_in,
                              void* d_out, int out_size) {
    const float* x = (const float*)d_in[0];
    const float* y = (const float*)d_in[1];
    float* out = (float*)d_out;

    normalize_kernel<<<2 * NROWS / 8, 256>>>(x, y);

    cudaFuncSetAttribute(gemm_hmma,
                         cudaFuncAttributeMaxDynamicSharedMemorySize, SMEM_TOTAL);
    dim3 grid(NROWS / BN, NROWS / BM);
    gemm_hmma<<<grid, 128, SMEM_TOTAL>>>(out);
}